// round 4
// baseline (speedup 1.0000x reference)
#include <cuda_runtime.h>
#include <math.h>

#define BATCH 4
#define SEQ   2048
#define EMD   768
#define HEADS 8
#define HDIM  96
#define MROWS (BATCH*SEQ)

#define TQ 16
#define TK 16
#define KSTR 772           // smem row stride (floats): 3088B, 16B-aligned
#define ESTR 17
#define SQRT_EMD 27.712812921102035f

typedef unsigned long long ull;

__device__ __forceinline__ ull pk2(float lo, float hi) {
    ull r; asm("mov.b64 %0,{%1,%2};" : "=l"(r) : "f"(lo), "f"(hi)); return r;
}
__device__ __forceinline__ void upk2(ull v, float& lo, float& hi) {
    asm("mov.b64 {%0,%1},%2;" : "=f"(lo), "=f"(hi) : "l"(v));
}
#define FFMA2(d,a,b,c) asm("fma.rn.f32x2 %0,%1,%2,%3;" : "=l"(d) : "l"(a), "l"(b), "l"(c))

// Scratch (allocation-free rule: __device__ globals)
__device__ float g_Q [MROWS*EMD];
__device__ float g_K [MROWS*EMD];
__device__ float g_V [MROWS*EMD];
__device__ float g_O [MROWS*EMD];   // attention partial O, k-half 0
__device__ float g_O2[MROWS*EMD];   // attention partial O, k-half 1

// ---------------------------------------------------------------------------
// GEMM: C[m,n] = sum_k (A[m,k] (+ A2[m,k])) * W[n,k] + bias[n]
// NT, fp32, FFMA2 core. 128x128 tile, BK=16, 256 threads, 8x8 microtile.
// A smem pre-packed as (a,a) ull pairs; B smem additive-swizzled.
// blockIdx.z selects one of up to 3 (W, bias, C) triples (fused QKV).
// ---------------------------------------------------------------------------
__global__ __launch_bounds__(256, 2)
void gemm_nt_bias(const float* __restrict__ A, const float* __restrict__ A2,
                  const float* __restrict__ W0, const float* __restrict__ bv0, float* __restrict__ C0,
                  const float* __restrict__ W1, const float* __restrict__ bv1, float* __restrict__ C1,
                  const float* __restrict__ W2, const float* __restrict__ bv2, float* __restrict__ C2)
{
    const float* W    = W0;
    const float* bias = bv0;
    float*       C    = C0;
    if (blockIdx.z == 1) { W = W1; bias = bv1; C = C1; }
    if (blockIdx.z == 2) { W = W2; bias = bv2; C = C2; }

    __shared__ __align__(16) ull   As2[16][128];   // (a,a) duplicated pairs
    __shared__ __align__(16) float Bs [16][136];   // 128 cols + swizzle headroom

    const int tid = threadIdx.x;
    const int tx  = tid & 15;
    const int ty  = tid >> 4;
    const int m0  = blockIdx.x * 128;
    const int n0  = blockIdx.y * 128;

    const int lr  = tid >> 1;                 // 0..127: tile row for loading
    const int lc  = (tid & 1) * 4;            // 0 or 4: k sub-offset (float4)
    const int bc  = lr + ((lr >> 5) << 1);    // swizzled B column for store
    const int txc = tx*8 + ((tx >> 2) << 1);  // swizzled B column for frag load

    const float* Ap  = A  + (size_t)(m0 + lr) * EMD + lc;
    const float* A2p = A2 ? (A2 + (size_t)(m0 + lr) * EMD + lc) : (const float*)0;
    const float* Wp  = W  + (size_t)(n0 + lr) * EMD + lc;

    ull acc[8][4];
    #pragma unroll
    for (int i = 0; i < 8; i++)
        #pragma unroll
        for (int j = 0; j < 4; j++) acc[i][j] = 0ull;

    for (int k0 = 0; k0 < EMD; k0 += 16) {
        #pragma unroll
        for (int half = 0; half < 16; half += 8) {
            float4 av = *(const float4*)(Ap + k0 + half);
            if (A2p) {
                const float4 a2v = *(const float4*)(A2p + k0 + half);
                av.x += a2v.x; av.y += a2v.y; av.z += a2v.z; av.w += a2v.w;
            }
            const float4 wv = *(const float4*)(Wp + k0 + half);
            As2[lc+half+0][lr] = pk2(av.x, av.x);
            As2[lc+half+1][lr] = pk2(av.y, av.y);
            As2[lc+half+2][lr] = pk2(av.z, av.z);
            As2[lc+half+3][lr] = pk2(av.w, av.w);
            Bs[lc+half+0][bc] = wv.x; Bs[lc+half+1][bc] = wv.y;
            Bs[lc+half+2][bc] = wv.z; Bs[lc+half+3][bc] = wv.w;
        }
        __syncthreads();

        #pragma unroll
        for (int k = 0; k < 16; k++) {
            ull a2[8];
            #pragma unroll
            for (int i = 0; i < 8; i++) a2[i] = As2[k][ty*8 + i];
            const ull* bp = (const ull*)&Bs[k][txc];
            const ull bb0 = bp[0], bb1 = bp[1], bb2 = bp[2], bb3 = bp[3];
            #pragma unroll
            for (int i = 0; i < 8; i++) {
                FFMA2(acc[i][0], a2[i], bb0, acc[i][0]);
                FFMA2(acc[i][1], a2[i], bb1, acc[i][1]);
                FFMA2(acc[i][2], a2[i], bb2, acc[i][2]);
                FFMA2(acc[i][3], a2[i], bb3, acc[i][3]);
            }
        }
        __syncthreads();
    }

    const float4 bi0 = *(const float4*)&bias[n0 + tx*8];
    const float4 bi1 = *(const float4*)&bias[n0 + tx*8 + 4];
    #pragma unroll
    for (int i = 0; i < 8; i++) {
        const int m = m0 + ty*8 + i;
        float c0,c1,c2,c3,c4,c5,c6,c7;
        upk2(acc[i][0], c0, c1); upk2(acc[i][1], c2, c3);
        upk2(acc[i][2], c4, c5); upk2(acc[i][3], c6, c7);
        float4 o0, o1;
        o0.x = c0 + bi0.x; o0.y = c1 + bi0.y; o0.z = c2 + bi0.z; o0.w = c3 + bi0.w;
        o1.x = c4 + bi1.x; o1.y = c5 + bi1.y; o1.z = c6 + bi1.z; o1.w = c7 + bi1.w;
        *(float4*)(C + (size_t)m * EMD + n0 + tx*8    ) = o0;
        *(float4*)(C + (size_t)m * EMD + n0 + tx*8 + 4) = o1;
    }
}

// ---------------------------------------------------------------------------
// Fused attention, softmax over HEADS axis. FFMA2 core, split-K.
// CTA: (b, 16-row q-tile, k-half). 8 warps = 1 per head, 2 CTAs/SM.
// Shared K/V buffer: K loaded for E phase, V loaded into the same buffer
// after the post-E barrier (softmax has no k-coupling, so split-K is exact).
// Lane: qg = lane>>3 (rows qg+4i, i<4), kg = lane&7 (k-cols {kg,kg+8};
// d-cols kg*12..+11 in the AV phase).
// ---------------------------------------------------------------------------
__global__ __launch_bounds__(256, 2)
void attn_kernel()
{
    extern __shared__ float sm[];
    float* Qs = sm;                       // TQ * KSTR
    float* KV = Qs + TQ*KSTR;             // TK * KSTR (K, then V)
    float* Es = KV + TK*KSTR;             // HEADS * TQ * ESTR

    const int b    = blockIdx.y;
    const int q0   = blockIdx.x * TQ;
    const int kh   = blockIdx.z;
    const int tid  = threadIdx.x;
    const int warp = tid >> 5;            // head index
    const int lane = tid & 31;
    const int qg   = lane >> 3;           // 0..3
    const int kg   = lane & 7;            // 0..7
    const int hb   = warp * HDIM;

    // Load Q tile (16 rows x 768 floats, all heads)
    for (int j = tid; j < TQ*(EMD/4); j += 256) {
        const int r = j / (EMD/4);
        const int c = (j % (EMD/4)) * 4;
        *(float4*)(Qs + r*KSTR + c) =
            *(const float4*)(g_Q + (size_t)(b*SEQ + q0 + r)*EMD + c);
    }

    ull Oacc[4][6];
    #pragma unroll
    for (int i = 0; i < 4; i++)
        #pragma unroll
        for (int j = 0; j < 6; j++) Oacc[i][j] = 0ull;

    const int kbeg = kh * (SEQ/2);
    for (int k0 = kbeg; k0 < kbeg + SEQ/2; k0 += TK) {
        __syncthreads();   // (a) prev AV reads of KV/Es done; Q visible (iter 0)

        // Load K tile into shared buffer
        for (int j = tid; j < TK*(EMD/4); j += 256) {
            const int r = j / (EMD/4);
            const int c = (j % (EMD/4)) * 4;
            *(float4*)(KV + r*KSTR + c) =
                *(const float4*)(g_K + (size_t)(b*SEQ + k0 + r)*EMD + c);
        }
        __syncthreads();   // (b)

        // ---- Energy: rows qg+4i (i<4), k-cols {kg, kg+8} ----
        ull e2[4][2];
        #pragma unroll
        for (int i = 0; i < 4; i++) { e2[i][0] = 0ull; e2[i][1] = 0ull; }

        const float* qbase  = Qs + (size_t)qg*KSTR + hb;
        const float* k0base = KV + (size_t)kg*KSTR + hb;
        const float* k1base = KV + (size_t)(kg+8)*KSTR + hb;

        #pragma unroll
        for (int d = 0; d < HDIM; d += 4) {
            const ulonglong2 kv0 = *(const ulonglong2*)(k0base + d);
            const ulonglong2 kv1 = *(const ulonglong2*)(k1base + d);
            #pragma unroll
            for (int i = 0; i < 4; i++) {
                const ulonglong2 qv = *(const ulonglong2*)(qbase + (size_t)(4*i)*KSTR + d);
                FFMA2(e2[i][0], qv.x, kv0.x, e2[i][0]);
                FFMA2(e2[i][0], qv.y, kv0.y, e2[i][0]);
                FFMA2(e2[i][1], qv.x, kv1.x, e2[i][1]);
                FFMA2(e2[i][1], qv.y, kv1.y, e2[i][1]);
            }
        }

        // exp -> Es
        #pragma unroll
        for (int i = 0; i < 4; i++) {
            float lo, hi;
            upk2(e2[i][0], lo, hi); const float s0 = lo + hi;
            upk2(e2[i][1], lo, hi); const float s1 = lo + hi;
            const int row = warp*TQ + qg + 4*i;
            Es[row*ESTR + kg    ] = __expf(s0);
            Es[row*ESTR + kg + 8] = __expf(s1);
        }
        __syncthreads();   // (c) all E reads of KV done; exp values visible

        // Load V tile into the same buffer (overlaps with normalize below)
        for (int j = tid; j < TK*(EMD/4); j += 256) {
            const int r = j / (EMD/4);
            const int c = (j % (EMD/4)) * 4;
            *(float4*)(KV + r*KSTR + c) =
                *(const float4*)(g_V + (size_t)(b*SEQ + k0 + r)*EMD + c);
        }

        // Cross-head denominator + in-place normalize: one (q,k) per thread
        {
            const int q = tid >> 4;
            const int k = tid & 15;
            float s = 0.f;
            #pragma unroll
            for (int h = 0; h < HEADS; h++) s += Es[(h*TQ + q)*ESTR + k];
            const float inv = 1.0f / (s * SQRT_EMD);
            #pragma unroll
            for (int h = 0; h < HEADS; h++) Es[(h*TQ + q)*ESTR + k] *= inv;
        }
        __syncthreads();   // (d) V stores + normalized Es visible

        // ---- O += A @ V : rows qg+4i, d-cols kg*12..+11 ----
        #pragma unroll
        for (int k = 0; k < TK; k++) {
            ull a2[4];
            #pragma unroll
            for (int i = 0; i < 4; i++) {
                const float av = Es[(warp*TQ + qg + 4*i)*ESTR + k];
                a2[i] = pk2(av, av);
            }
            const float* vp = KV + (size_t)k*KSTR + hb + kg*12;
            const ulonglong2 v0 = *(const ulonglong2*)(vp + 0);
            const ulonglong2 v1 = *(const ulonglong2*)(vp + 4);
            const ulonglong2 v2 = *(const ulonglong2*)(vp + 8);
            #pragma unroll
            for (int i = 0; i < 4; i++) {
                FFMA2(Oacc[i][0], a2[i], v0.x, Oacc[i][0]);
                FFMA2(Oacc[i][1], a2[i], v0.y, Oacc[i][1]);
                FFMA2(Oacc[i][2], a2[i], v1.x, Oacc[i][2]);
                FFMA2(Oacc[i][3], a2[i], v1.y, Oacc[i][3]);
                FFMA2(Oacc[i][4], a2[i], v2.x, Oacc[i][4]);
                FFMA2(Oacc[i][5], a2[i], v2.y, Oacc[i][5]);
            }
        }
    }

    // Write partial O in [M, 768] layout (col = h*96 + d)
    float* Obase = kh ? g_O2 : g_O;
    #pragma unroll
    for (int i = 0; i < 4; i++) {
        float* op = Obase + (size_t)(b*SEQ + q0 + qg + 4*i)*EMD + hb + kg*12;
        float f[12];
        upk2(Oacc[i][0], f[0], f[1]);  upk2(Oacc[i][1], f[2],  f[3]);
        upk2(Oacc[i][2], f[4], f[5]);  upk2(Oacc[i][3], f[6],  f[7]);
        upk2(Oacc[i][4], f[8], f[9]);  upk2(Oacc[i][5], f[10], f[11]);
        float4 o0, o1, o2;
        o0.x=f[0]; o0.y=f[1]; o0.z=f[2];  o0.w=f[3];
        o1.x=f[4]; o1.y=f[5]; o1.z=f[6];  o1.w=f[7];
        o2.x=f[8]; o2.y=f[9]; o2.z=f[10]; o2.w=f[11];
        *(float4*)(op + 0) = o0;
        *(float4*)(op + 4) = o1;
        *(float4*)(op + 8) = o2;
    }
}

// ---------------------------------------------------------------------------
extern "C" void kernel_launch(void* const* d_in, const int* in_sizes, int n_in,
                              void* d_out, int out_size)
{
    const float* x  = (const float*)d_in[0];
    const float* Wq = (const float*)d_in[1];
    const float* bq = (const float*)d_in[2];
    const float* Wk = (const float*)d_in[3];
    const float* bk = (const float*)d_in[4];
    const float* Wv = (const float*)d_in[5];
    const float* bv = (const float*)d_in[6];
    const float* Wo = (const float*)d_in[7];
    const float* bo = (const float*)d_in[8];
    float* out = (float*)d_out;

    float *Qp, *Kp, *Vp, *Op, *O2p;
    cudaGetSymbolAddress((void**)&Qp,  g_Q);
    cudaGetSymbolAddress((void**)&Kp,  g_K);
    cudaGetSymbolAddress((void**)&Vp,  g_V);
    cudaGetSymbolAddress((void**)&Op,  g_O);
    cudaGetSymbolAddress((void**)&O2p, g_O2);

    const int smem_bytes = ((TQ + TK)*KSTR + HEADS*TQ*ESTR) * (int)sizeof(float); // 107520
    cudaFuncSetAttribute(attn_kernel, cudaFuncAttributeMaxDynamicSharedMemorySize, smem_bytes);

    // 1) Fused QKV projections (z selects Q/K/V)
    gemm_nt_bias<<<dim3(MROWS/128, EMD/128, 3), 256>>>(
        x, (const float*)0, Wq, bq, Qp, Wk, bk, Kp, Wv, bv, Vp);

    // 2) Fused head-axis-softmax attention, split-K (2 halves)
    attn_kernel<<<dim3(SEQ/TQ, BATCH, 2), 256, smem_bytes>>>();

    // 3) Output projection -> d_out (A = g_O + g_O2)
    gemm_nt_bias<<<dim3(MROWS/128, EMD/128, 1), 256>>>(
        Op, O2p, Wo, bo, out, Wo, bo, out, Wo, bo, out);
}

// round 5
// speedup vs baseline: 1.1626x; 1.1626x over previous
#include <cuda_runtime.h>
#include <math.h>

#define BATCH 4
#define SEQ   2048
#define EMD   768
#define HEADS 8
#define HDIM  96
#define MROWS (BATCH*SEQ)

#define TQ 32
#define TK 16
#define KSPLIT 4
#define KCHUNK (SEQ/KSPLIT)
#define KSTR 772           // smem row stride (floats): 3088B, 16B-aligned, bank-staggered
#define ESTR 17
#define SQRT_EMD 27.712812921102035f

typedef unsigned long long ull;

__device__ __forceinline__ ull pk2(float lo, float hi) {
    ull r; asm("mov.b64 %0,{%1,%2};" : "=l"(r) : "f"(lo), "f"(hi)); return r;
}
__device__ __forceinline__ void upk2(ull v, float& lo, float& hi) {
    asm("mov.b64 {%0,%1},%2;" : "=f"(lo), "=f"(hi) : "l"(v));
}
#define FFMA2(d,a,b,c) asm("fma.rn.f32x2 %0,%1,%2,%3;" : "=l"(d) : "l"(a), "l"(b), "l"(c))

// Scratch (allocation-free rule: __device__ globals)
__device__ float g_Q [MROWS*EMD];
__device__ float g_K [MROWS*EMD];
__device__ float g_V [MROWS*EMD];
__device__ float g_O0[MROWS*EMD];   // attention partial O, k-quarter 0..3
__device__ float g_O1[MROWS*EMD];
__device__ float g_O2[MROWS*EMD];
__device__ float g_O3[MROWS*EMD];

// ---------------------------------------------------------------------------
// Shared GEMM epilogue/微tile layout:
// 128x128 tile, BK=8, 256 threads, 8x8 microtile as 8x4 f32x2 pairs.
// A smem pre-packed (a,a) ull at fill time; B smem additively swizzled.
// Register prefetch of next k-slab issued right after the first barrier.
// ---------------------------------------------------------------------------

// QKV projections: C_z[m,n] = sum_k x[m,k]*W_z[n,k] + b_z[n], z in {0,1,2}
__global__ __launch_bounds__(256)
void gemm_qkv(const float* __restrict__ A,
              const float* __restrict__ W0, const float* __restrict__ bv0, float* __restrict__ C0,
              const float* __restrict__ W1, const float* __restrict__ bv1, float* __restrict__ C1,
              const float* __restrict__ W2, const float* __restrict__ bv2, float* __restrict__ C2)
{
    const float* W    = W0;
    const float* bias = bv0;
    float*       C    = C0;
    if (blockIdx.z == 1) { W = W1; bias = bv1; C = C1; }
    if (blockIdx.z == 2) { W = W2; bias = bv2; C = C2; }

    __shared__ __align__(16) ull   As2[8][128];
    __shared__ __align__(16) float Bs [8][136];

    const int tid = threadIdx.x;
    const int tx  = tid & 15;
    const int ty  = tid >> 4;
    const int m0  = blockIdx.x * 128;
    const int n0  = blockIdx.y * 128;

    const int lr  = tid >> 1;
    const int lc  = (tid & 1) * 4;
    const int bc  = lr + ((lr >> 5) << 1);
    const int txc = tx*8 + ((tx >> 2) << 1);

    const float* Ap = A + (size_t)(m0 + lr) * EMD + lc;
    const float* Wp = W + (size_t)(n0 + lr) * EMD + lc;

    ull acc[8][4];
    #pragma unroll
    for (int i = 0; i < 8; i++)
        #pragma unroll
        for (int j = 0; j < 4; j++) acc[i][j] = 0ull;

    float4 av = *(const float4*)(Ap);
    float4 wv = *(const float4*)(Wp);

    for (int k0 = 0; k0 < EMD; k0 += 8) {
        As2[lc+0][lr] = pk2(av.x, av.x);
        As2[lc+1][lr] = pk2(av.y, av.y);
        As2[lc+2][lr] = pk2(av.z, av.z);
        As2[lc+3][lr] = pk2(av.w, av.w);
        Bs[lc+0][bc] = wv.x; Bs[lc+1][bc] = wv.y;
        Bs[lc+2][bc] = wv.z; Bs[lc+3][bc] = wv.w;
        __syncthreads();

        if (k0 + 8 < EMD) {                         // prefetch next slab
            av = *(const float4*)(Ap + k0 + 8);
            wv = *(const float4*)(Wp + k0 + 8);
        }

        #pragma unroll
        for (int k = 0; k < 8; k++) {
            ull a2[8];
            #pragma unroll
            for (int i = 0; i < 8; i++) a2[i] = As2[k][ty*8 + i];
            const ull* bp = (const ull*)&Bs[k][txc];
            const ull bb0 = bp[0], bb1 = bp[1], bb2 = bp[2], bb3 = bp[3];
            #pragma unroll
            for (int i = 0; i < 8; i++) {
                FFMA2(acc[i][0], a2[i], bb0, acc[i][0]);
                FFMA2(acc[i][1], a2[i], bb1, acc[i][1]);
                FFMA2(acc[i][2], a2[i], bb2, acc[i][2]);
                FFMA2(acc[i][3], a2[i], bb3, acc[i][3]);
            }
        }
        __syncthreads();
    }

    const float4 bi0 = *(const float4*)&bias[n0 + tx*8];
    const float4 bi1 = *(const float4*)&bias[n0 + tx*8 + 4];
    #pragma unroll
    for (int i = 0; i < 8; i++) {
        const int m = m0 + ty*8 + i;
        float c0,c1,c2,c3,c4,c5,c6,c7;
        upk2(acc[i][0], c0, c1); upk2(acc[i][1], c2, c3);
        upk2(acc[i][2], c4, c5); upk2(acc[i][3], c6, c7);
        float4 o0, o1;
        o0.x = c0 + bi0.x; o0.y = c1 + bi0.y; o0.z = c2 + bi0.z; o0.w = c3 + bi0.w;
        o1.x = c4 + bi1.x; o1.y = c5 + bi1.y; o1.z = c6 + bi1.z; o1.w = c7 + bi1.w;
        *(float4*)(C + (size_t)m * EMD + n0 + tx*8    ) = o0;
        *(float4*)(C + (size_t)m * EMD + n0 + tx*8 + 4) = o1;
    }
}

// Output projection: C[m,n] = sum_k (O0+O1+O2+O3)[m,k] * Wo[n,k] + bo[n]
__global__ __launch_bounds__(256)
void gemm_out(const float* __restrict__ A0, const float* __restrict__ A1,
              const float* __restrict__ A2p, const float* __restrict__ A3,
              const float* __restrict__ W, const float* __restrict__ bias,
              float* __restrict__ C)
{
    __shared__ __align__(16) ull   As2[8][128];
    __shared__ __align__(16) float Bs [8][136];

    const int tid = threadIdx.x;
    const int tx  = tid & 15;
    const int ty  = tid >> 4;
    const int m0  = blockIdx.x * 128;
    const int n0  = blockIdx.y * 128;

    const int lr  = tid >> 1;
    const int lc  = (tid & 1) * 4;
    const int bc  = lr + ((lr >> 5) << 1);
    const int txc = tx*8 + ((tx >> 2) << 1);

    const size_t aoff = (size_t)(m0 + lr) * EMD + lc;
    const float* Wp = W + (size_t)(n0 + lr) * EMD + lc;

    ull acc[8][4];
    #pragma unroll
    for (int i = 0; i < 8; i++)
        #pragma unroll
        for (int j = 0; j < 4; j++) acc[i][j] = 0ull;

    float4 a0 = *(const float4*)(A0 + aoff);
    float4 a1 = *(const float4*)(A1 + aoff);
    float4 a2 = *(const float4*)(A2p + aoff);
    float4 a3 = *(const float4*)(A3 + aoff);
    float4 wv = *(const float4*)(Wp);

    for (int k0 = 0; k0 < EMD; k0 += 8) {
        float4 av;
        av.x = (a0.x + a1.x) + (a2.x + a3.x);
        av.y = (a0.y + a1.y) + (a2.y + a3.y);
        av.z = (a0.z + a1.z) + (a2.z + a3.z);
        av.w = (a0.w + a1.w) + (a2.w + a3.w);
        As2[lc+0][lr] = pk2(av.x, av.x);
        As2[lc+1][lr] = pk2(av.y, av.y);
        As2[lc+2][lr] = pk2(av.z, av.z);
        As2[lc+3][lr] = pk2(av.w, av.w);
        Bs[lc+0][bc] = wv.x; Bs[lc+1][bc] = wv.y;
        Bs[lc+2][bc] = wv.z; Bs[lc+3][bc] = wv.w;
        __syncthreads();

        if (k0 + 8 < EMD) {
            a0 = *(const float4*)(A0 + aoff + k0 + 8);
            a1 = *(const float4*)(A1 + aoff + k0 + 8);
            a2 = *(const float4*)(A2p + aoff + k0 + 8);
            a3 = *(const float4*)(A3 + aoff + k0 + 8);
            wv = *(const float4*)(Wp + k0 + 8);
        }

        #pragma unroll
        for (int k = 0; k < 8; k++) {
            ull a2r[8];
            #pragma unroll
            for (int i = 0; i < 8; i++) a2r[i] = As2[k][ty*8 + i];
            const ull* bp = (const ull*)&Bs[k][txc];
            const ull bb0 = bp[0], bb1 = bp[1], bb2 = bp[2], bb3 = bp[3];
            #pragma unroll
            for (int i = 0; i < 8; i++) {
                FFMA2(acc[i][0], a2r[i], bb0, acc[i][0]);
                FFMA2(acc[i][1], a2r[i], bb1, acc[i][1]);
                FFMA2(acc[i][2], a2r[i], bb2, acc[i][2]);
                FFMA2(acc[i][3], a2r[i], bb3, acc[i][3]);
            }
        }
        __syncthreads();
    }

    const float4 bi0 = *(const float4*)&bias[n0 + tx*8];
    const float4 bi1 = *(const float4*)&bias[n0 + tx*8 + 4];
    #pragma unroll
    for (int i = 0; i < 8; i++) {
        const int m = m0 + ty*8 + i;
        float c0,c1,c2,c3,c4,c5,c6,c7;
        upk2(acc[i][0], c0, c1); upk2(acc[i][1], c2, c3);
        upk2(acc[i][2], c4, c5); upk2(acc[i][3], c6, c7);
        float4 o0, o1;
        o0.x = c0 + bi0.x; o0.y = c1 + bi0.y; o0.z = c2 + bi0.z; o0.w = c3 + bi0.w;
        o1.x = c4 + bi1.x; o1.y = c5 + bi1.y; o1.z = c6 + bi1.z; o1.w = c7 + bi1.w;
        *(float4*)(C + (size_t)m * EMD + n0 + tx*8    ) = o0;
        *(float4*)(C + (size_t)m * EMD + n0 + tx*8 + 4) = o1;
    }
}

// ---------------------------------------------------------------------------
// Fused attention, softmax over HEADS axis. FFMA2 core, split-K4 (exact:
// the head-softmax has no coupling across k, partial O sums in gemm_out).
// CTA: (b, 32-row q-tile, k-quarter). 8 warps = 1 per head.
// Lane: qg = lane>>3 (rows qg+4i, i<8), kg = lane&7 (k-cols {kg,kg+8};
// d-cols kg*12..+11 in the AV phase).
// ---------------------------------------------------------------------------
__global__ __launch_bounds__(256)
void attn_kernel()
{
    extern __shared__ float sm[];
    float* Qs = sm;                       // TQ * KSTR
    float* Ks = Qs + TQ*KSTR;             // TK * KSTR
    float* Vs = Ks + TK*KSTR;             // TK * KSTR
    float* Es = Vs + TK*KSTR;             // HEADS * TQ * ESTR

    const int b    = blockIdx.y;
    const int q0   = blockIdx.x * TQ;
    const int kh   = blockIdx.z;
    const int tid  = threadIdx.x;
    const int warp = tid >> 5;            // head index
    const int lane = tid & 31;
    const int qg   = lane >> 3;           // 0..3
    const int kg   = lane & 7;            // 0..7
    const int hb   = warp * HDIM;

    // Load Q tile (32 rows x 768 floats, all heads)
    for (int j = tid; j < TQ*(EMD/4); j += 256) {
        const int r = j / (EMD/4);
        const int c = (j % (EMD/4)) * 4;
        *(float4*)(Qs + r*KSTR + c) =
            *(const float4*)(g_Q + (size_t)(b*SEQ + q0 + r)*EMD + c);
    }

    ull Oacc[8][6];
    #pragma unroll
    for (int i = 0; i < 8; i++)
        #pragma unroll
        for (int j = 0; j < 6; j++) Oacc[i][j] = 0ull;

    const int kbeg = kh * KCHUNK;
    for (int k0 = kbeg; k0 < kbeg + KCHUNK; k0 += TK) {
        __syncthreads();   // prev AV reads of Ks/Vs/Es done; Q visible (iter 0)

        for (int j = tid; j < TK*(EMD/4); j += 256) {
            const int r = j / (EMD/4);
            const int c = (j % (EMD/4)) * 4;
            const size_t g = (size_t)(b*SEQ + k0 + r)*EMD + c;
            *(float4*)(Ks + r*KSTR + c) = *(const float4*)(g_K + g);
            *(float4*)(Vs + r*KSTR + c) = *(const float4*)(g_V + g);
        }
        __syncthreads();

        // ---- Energy: rows qg+4i (i=0..7), k-cols {kg, kg+8} ----
        ull e2[8][2];
        #pragma unroll
        for (int i = 0; i < 8; i++) { e2[i][0] = 0ull; e2[i][1] = 0ull; }

        const float* qbase  = Qs + (size_t)qg*KSTR + hb;
        const float* k0base = Ks + (size_t)kg*KSTR + hb;
        const float* k1base = Ks + (size_t)(kg+8)*KSTR + hb;

        #pragma unroll
        for (int d = 0; d < HDIM; d += 4) {
            const ulonglong2 kv0 = *(const ulonglong2*)(k0base + d);
            const ulonglong2 kv1 = *(const ulonglong2*)(k1base + d);
            #pragma unroll
            for (int i = 0; i < 8; i++) {
                const ulonglong2 qv = *(const ulonglong2*)(qbase + (size_t)(4*i)*KSTR + d);
                FFMA2(e2[i][0], qv.x, kv0.x, e2[i][0]);
                FFMA2(e2[i][0], qv.y, kv0.y, e2[i][0]);
                FFMA2(e2[i][1], qv.x, kv1.x, e2[i][1]);
                FFMA2(e2[i][1], qv.y, kv1.y, e2[i][1]);
            }
        }

        // exp -> Es
        #pragma unroll
        for (int i = 0; i < 8; i++) {
            float lo, hi;
            upk2(e2[i][0], lo, hi); const float s0 = lo + hi;
            upk2(e2[i][1], lo, hi); const float s1 = lo + hi;
            const int row = warp*TQ + qg + 4*i;
            Es[row*ESTR + kg    ] = __expf(s0);
            Es[row*ESTR + kg + 8] = __expf(s1);
        }
        __syncthreads();

        // Cross-head denominator + in-place normalize: 2 (q,k) pairs / thread
        #pragma unroll
        for (int pp = 0; pp < 2; pp++) {
            const int p = tid*2 + pp;
            const int q = p >> 4;
            const int k = p & 15;
            float s = 0.f;
            #pragma unroll
            for (int h = 0; h < HEADS; h++) s += Es[(h*TQ + q)*ESTR + k];
            const float inv = 1.0f / (s * SQRT_EMD);
            #pragma unroll
            for (int h = 0; h < HEADS; h++) Es[(h*TQ + q)*ESTR + k] *= inv;
        }
        __syncthreads();

        // ---- O += A @ V : rows qg+4i, d-cols kg*12..+11 ----
        #pragma unroll
        for (int k = 0; k < TK; k++) {
            ull a2[8];
            #pragma unroll
            for (int i = 0; i < 8; i++) {
                const float av = Es[(warp*TQ + qg + 4*i)*ESTR + k];
                a2[i] = pk2(av, av);
            }
            const float* vp = Vs + (size_t)k*KSTR + hb + kg*12;
            const ulonglong2 v0 = *(const ulonglong2*)(vp + 0);
            const ulonglong2 v1 = *(const ulonglong2*)(vp + 4);
            const ulonglong2 v2 = *(const ulonglong2*)(vp + 8);
            #pragma unroll
            for (int i = 0; i < 8; i++) {
                FFMA2(Oacc[i][0], a2[i], v0.x, Oacc[i][0]);
                FFMA2(Oacc[i][1], a2[i], v0.y, Oacc[i][1]);
                FFMA2(Oacc[i][2], a2[i], v1.x, Oacc[i][2]);
                FFMA2(Oacc[i][3], a2[i], v1.y, Oacc[i][3]);
                FFMA2(Oacc[i][4], a2[i], v2.x, Oacc[i][4]);
                FFMA2(Oacc[i][5], a2[i], v2.y, Oacc[i][5]);
            }
        }
    }

    // Write partial O in [M, 768] layout (col = h*96 + d)
    float* Obase = (kh == 0) ? g_O0 : (kh == 1) ? g_O1 : (kh == 2) ? g_O2 : g_O3;
    #pragma unroll
    for (int i = 0; i < 8; i++) {
        float* op = Obase + (size_t)(b*SEQ + q0 + qg + 4*i)*EMD + hb + kg*12;
        float f[12];
        upk2(Oacc[i][0], f[0], f[1]);  upk2(Oacc[i][1], f[2],  f[3]);
        upk2(Oacc[i][2], f[4], f[5]);  upk2(Oacc[i][3], f[6],  f[7]);
        upk2(Oacc[i][4], f[8], f[9]);  upk2(Oacc[i][5], f[10], f[11]);
        float4 o0, o1, o2;
        o0.x=f[0]; o0.y=f[1]; o0.z=f[2];  o0.w=f[3];
        o1.x=f[4]; o1.y=f[5]; o1.z=f[6];  o1.w=f[7];
        o2.x=f[8]; o2.y=f[9]; o2.z=f[10]; o2.w=f[11];
        *(float4*)(op + 0) = o0;
        *(float4*)(op + 4) = o1;
        *(float4*)(op + 8) = o2;
    }
}

// ---------------------------------------------------------------------------
extern "C" void kernel_launch(void* const* d_in, const int* in_sizes, int n_in,
                              void* d_out, int out_size)
{
    const float* x  = (const float*)d_in[0];
    const float* Wq = (const float*)d_in[1];
    const float* bq = (const float*)d_in[2];
    const float* Wk = (const float*)d_in[3];
    const float* bk = (const float*)d_in[4];
    const float* Wv = (const float*)d_in[5];
    const float* bv = (const float*)d_in[6];
    const float* Wo = (const float*)d_in[7];
    const float* bo = (const float*)d_in[8];
    float* out = (float*)d_out;

    float *Qp, *Kp, *Vp, *O0p, *O1p, *O2p, *O3p;
    cudaGetSymbolAddress((void**)&Qp,  g_Q);
    cudaGetSymbolAddress((void**)&Kp,  g_K);
    cudaGetSymbolAddress((void**)&Vp,  g_V);
    cudaGetSymbolAddress((void**)&O0p, g_O0);
    cudaGetSymbolAddress((void**)&O1p, g_O1);
    cudaGetSymbolAddress((void**)&O2p, g_O2);
    cudaGetSymbolAddress((void**)&O3p, g_O3);

    const int smem_bytes = ((TQ + 2*TK)*KSTR + HEADS*TQ*ESTR) * (int)sizeof(float); // 215040
    cudaFuncSetAttribute(attn_kernel, cudaFuncAttributeMaxDynamicSharedMemorySize, smem_bytes);

    // 1) Fused QKV projections (z selects Q/K/V)
    gemm_qkv<<<dim3(MROWS/128, EMD/128, 3), 256>>>(
        x, Wq, bq, Qp, Wk, bk, Kp, Wv, bv, Vp);

    // 2) Fused head-axis-softmax attention, split-K4 -> 1024 CTAs (wave-balanced)
    attn_kernel<<<dim3(SEQ/TQ, BATCH, KSPLIT), 256, smem_bytes>>>();

    // 3) Output projection -> d_out (A = sum of 4 partial O buffers)
    gemm_out<<<dim3(MROWS/128, EMD/128), 256>>>(
        O0p, O1p, O2p, O3p, Wo, bo, out);
}